// round 16
// baseline (speedup 1.0000x reference)
#include <cuda_runtime.h>
#include <cuda_fp16.h>
#include <cstdint>

// ---------------------------------------------------------------------------
// MultiLevelFeatureSampler on GB300 (sm_103a via base-target sm_103 SASS)
//
// Per point: D[128x256] = P[128x83] @ W^T (+ bias); P = gather of 83 taps.
// Two-product fp16: A -> fp16; B -> fp16 split (bh, bl); D = a*bh + a*bl.
// (rel_err 2.06e-4, measured.)
//
// R16: 2 CO-RESIDENT CTAs/SM (grid 296, 256 thr, ~107KB smem each).
// CTA pair (bid, bid+148) shares an SM and splits N of the SAME points:
// half0 = cols 0..127, half1 = cols 128..255.  Each CTA: resident B-half,
// double-buffered fp16 A, direct LDG gather (no raw/convert phases, one
// __syncthreads per point; taps double-buffered, computed 2 points ahead).
// half0 orders gather-then-MMA, half1 MMA-then-gather => the twins are
// anti-phased, so each CTA's LDG-stall window is covered by the sibling's
// MMA window.  st.global.cs epilogue.
// ---------------------------------------------------------------------------

#define NSM   148
#define NPTS_TOTAL 2048
#define CCH   128
#define DTOT  83
#define GTOT  (CCH * DTOT)     // 10624 gather elements per point
#define STRD  104              // A row stride in fp16 (208 B, conflict-free)
#define NOUT  256
#define NTHR  256

#define H0 93
#define W0 305
#define H1 47
#define W1 153
#define H2 24
#define W2 77

// ---- smem layout (bytes) ----
#define OFF_TAPP    0                              // 2 x 83 x 16B tap tables
#define TAP_BUF     1344                           // bytes per tap table slot
#define OFF_BIAS    2688                           // 128 * 4B (this half)
#define OFF_A       3328                           // 2 x 128x208 = 53248
#define ABUF        (CCH * STRD * 2)               // 26624
#define OFF_BH      (OFF_A + 2 * ABUF)             // 56576 (128 x 208B)
#define OFF_BL      (OFF_BH + CCH * STRD * 2)      // 83200
#define SMEM_TOTAL  (OFF_BL + CCH * STRD * 2)      // 109824 (~107.25 KB)

// W split-fp16 scratch, [0]=hi, [1]=lo, row-major 256 x STRD (pads zeroed)
__device__ __align__(16) __half g_B[2][NOUT * STRD];

// ---------------------------------------------------------------------------
__device__ __forceinline__ uint32_t smem_u32(const void* p) {
    uint32_t a;
    asm("{ .reg .u64 t; cvta.to.shared.u64 t, %1; cvt.u32.u64 %0, t; }"
        : "=r"(a) : "l"(p));
    return a;
}

__device__ __forceinline__ void cp16(uint32_t dst, const void* src) {
    asm volatile("cp.async.cg.shared.global [%0], [%1], 16;"
                 :: "r"(dst), "l"(src) : "memory");
}

__device__ __forceinline__ void ldsm4(uint32_t* r, uint32_t addr) {
    asm volatile("ldmatrix.sync.aligned.m8n8.x4.shared.b16 {%0,%1,%2,%3}, [%4];"
                 : "=r"(r[0]), "=r"(r[1]), "=r"(r[2]), "=r"(r[3]) : "r"(addr));
}

__device__ __forceinline__ void hmma(float* c, const uint32_t* a, const uint32_t* b) {
    asm volatile(
        "mma.sync.aligned.m16n8k16.row.col.f32.f16.f16.f32 "
        "{%0,%1,%2,%3}, {%4,%5,%6,%7}, {%8,%9}, {%0,%1,%2,%3};"
        : "+f"(c[0]), "+f"(c[1]), "+f"(c[2]), "+f"(c[3])
        : "r"(a[0]), "r"(a[1]), "r"(a[2]), "r"(a[3]), "r"(b[0]), "r"(b[1]));
}

__device__ __forceinline__ void stcs2(float* p, float x, float y) {
    asm volatile("st.global.cs.v2.f32 [%0], {%1, %2};"
                 :: "l"(p), "f"(x), "f"(y) : "memory");
}

// Per-tap metadata for point pn (d < 83) into tap table tb.
// Entry: 16B = { const float* ptr (8B), int stride (4B), pad }.
__device__ __forceinline__ void compute_taps(char* smem, int tb, int d, int pn,
                                             const float* __restrict__ points,
                                             const float* __restrict__ feat0,
                                             const float* __restrict__ feat1,
                                             const float* __restrict__ feat2) {
    const float* f; int H, Wd, ks, dd;
    if (d < 49)      { f = feat0; H = H0; Wd = W0; ks = 7; dd = d; }
    else if (d < 74) { f = feat1; H = H1; Wd = W1; ks = 5; dd = d - 49; }
    else             { f = feat2; H = H2; Wd = W2; ks = 3; dd = d - 74; }
    int half = ks >> 1;
    int jj = dd / ks - half;
    int kk = dd % ks - half;
    int bi = pn >> 9;
    float px = points[pn * 2 + 0];
    float py = points[pn * 2 + 1];
    float x = fminf(fmaxf(px * (float)(Wd - 1), 0.f), (float)(Wd - 1));
    float y = fminf(fmaxf(py * (float)(H  - 1), 0.f), (float)(H  - 1));
    int ox = (int)floorf(fminf(fmaxf(x + (float)kk, 0.f), (float)(Wd - 1)));
    int oy = (int)floorf(fminf(fmaxf(y + (float)jj, 0.f), (float)(H  - 1)));
    char* ent = smem + OFF_TAPP + tb * TAP_BUF + d * 16;
    *(const float**)(ent) = f + (size_t)bi * CCH * H * Wd + (oy * Wd + ox);
    *(int*)(ent + 8) = H * Wd;
}

// Gather + fp16-convert one point into A buffer (direct LDG; stalls covered
// by the sibling CTA's MMA).  256 threads; e = tid + 256*i; 256 = 3*83 + 7.
__device__ __forceinline__ void gather_point(char* smem, int tb, char* dstA,
                                             int tid) {
    const char* tbl = smem + OFF_TAPP + tb * TAP_BUF;
    int c = tid / DTOT;
    int d = tid - c * DTOT;
    #pragma unroll 1
    for (int base = 0; base < GTOT; base += 256 * 7) {
        float v[7]; int cc[7], dd[7]; bool ok[7];
        #pragma unroll
        for (int j = 0; j < 7; ++j) {
            int e = tid + base + j * 256;
            ok[j] = (e < GTOT);
            if (ok[j]) {
                uint4 te = *(const uint4*)(tbl + d * 16);
                const float* bp;
                asm("mov.b64 %0, {%1, %2};" : "=l"(bp) : "r"(te.x), "r"(te.y));
                v[j] = __ldg(bp + (size_t)c * (int)te.z);
                cc[j] = c; dd[j] = d;
            }
            c += 3; d += 7;
            if (d >= DTOT) { d -= DTOT; c += 1; }
        }
        #pragma unroll
        for (int j = 0; j < 7; ++j)
            if (ok[j])
                *(__half*)(dstA + cc[j] * 208 + dd[j] * 2) = __float2half(v[j]);
    }
}

// ---------------------------------------------------------------------------
// Prologue: W (256x83 fp32) -> g_B hi/lo fp16, row stride STRD, pads zeroed.
__global__ void prep_B_kernel(const float* __restrict__ Wg) {
    int idx = blockIdx.x * 256 + threadIdx.x;
    if (idx >= NOUT * STRD) return;
    int row = idx / STRD;
    int col = idx - row * STRD;
    float v = (col < DTOT) ? Wg[row * DTOT + col] : 0.f;
    __half hi = __float2half(v);
    __half lo = __float2half(v - __half2float(hi));
    g_B[0][idx] = hi;
    g_B[1][idx] = lo;
}

// ---------------------------------------------------------------------------
__global__ void __launch_bounds__(NTHR, 2)
mlfs_kernel(const float* __restrict__ points,
            const float* __restrict__ feat0,
            const float* __restrict__ feat1,
            const float* __restrict__ feat2,
            const float* __restrict__ biasg,
            float* __restrict__ out) {
    extern __shared__ char smem[];
    const uint32_t smem_base = smem_u32(smem);
    const int tid = threadIdx.x;
    const int wid = tid >> 5;
    const int lane = tid & 31;
    const int pr = blockIdx.x % NSM;        // point stride id
    const int nh = blockIdx.x / NSM;        // N half: 0 or 1

    // ---- setup: B-half resident copy (async), bias, A-pad zero ----
    {
        const char* srcH = (const char*)g_B[0] + nh * (CCH * STRD * 2);
        const char* srcL = (const char*)g_B[1] + nh * (CCH * STRD * 2);
        const int n16 = (CCH * STRD * 2) / 16;     // 1664 per matrix
        uint32_t dstH = smem_base + OFF_BH;
        uint32_t dstL = smem_base + OFF_BL;
        #pragma unroll 2
        for (int i = tid; i < n16; i += NTHR) {
            cp16(dstH + i * 16, srcH + (size_t)i * 16);
            cp16(dstL + i * 16, srcL + (size_t)i * 16);
        }
        asm volatile("cp.async.commit_group;" ::: "memory");
    }
    if (tid < 32)
        ((float4*)(smem + OFF_BIAS))[tid] =
            ((const float4*)(biasg + nh * 128))[tid];

    // zero A pad bytes 160..207 of every row, both buffers (256 rows total;
    // gather rewrites cols 80..82 = bytes 160..165 every point)
    {
        float4 z = make_float4(0.f, 0.f, 0.f, 0.f);
        char* base = smem + OFF_A + (tid >> 7) * ABUF + (tid & 127) * 208 + 160;
        ((float4*)base)[0] = z; ((float4*)base)[1] = z; ((float4*)base)[2] = z;
    }

    // taps(p0) -> T[0]; gather p0 -> A[0]; taps(p1) -> T[1]
    if (tid < DTOT)
        compute_taps(smem, 0, tid, pr, points, feat0, feat1, feat2);
    __syncthreads();
    gather_point(smem, 0, smem + OFF_A, tid);
    if (tid < DTOT && pr + NSM < NPTS_TOTAL)
        compute_taps(smem, 1, tid, pr + NSM, points, feat0, feat1, feat2);
    asm volatile("cp.async.wait_group 0;" ::: "memory");   // B resident

    // ---- persistent loop: one __syncthreads per point ----
    const int wm = wid >> 2;            // 0..1 (M, 64-row tiles)
    const int wn = wid & 3;             // 0..3 (N, 32-col tiles)
    const uint32_t lrow = lane & 15;
    const uint32_t kof2 = ((lane >> 4) << 3) * 2;
    const float* bs = (const float*)(smem + OFF_BIAS);

    int cur = 0;
    for (int p = pr; p < NPTS_TOTAL; p += NSM) {
        __syncthreads();   // A[cur] gathered; T[cur^1] ready; prior MMA done

        const bool hasnext = (p + NSM < NPTS_TOTAL);
        char* An = smem + OFF_A + (cur ^ 1) * ABUF;

        // half0: gather first (sibling is in MMA); half1: MMA first.
        if (nh == 0 && hasnext)
            gather_point(smem, cur ^ 1, An, tid);
        if (tid < DTOT && p + 2 * NSM < NPTS_TOTAL)
            compute_taps(smem, cur, tid, p + 2 * NSM,
                         points, feat0, feat1, feat2);

        // ---- two-product MMA on A[cur] (128 x 128 half-GEMM) ----
        {
            float acc[4][4][4];
            #pragma unroll
            for (int mt = 0; mt < 4; ++mt)
                #pragma unroll
                for (int nt = 0; nt < 4; ++nt)
                    #pragma unroll
                    for (int q = 0; q < 4; ++q) acc[mt][nt][q] = 0.f;

            const uint32_t aAddr0 = smem_base + OFF_A + cur * ABUF
                                  + (wm * 64 + lrow) * 208 + kof2;
            const uint32_t bAddr0 = smem_base + OFF_BH
                                  + (wn * 32 + lrow) * 208 + kof2;
            #pragma unroll
            for (int ks = 0; ks < 6; ++ks) {
                uint32_t a[4][4], bh[4][2], bl[4][2], t[4];
                #pragma unroll
                for (int mt = 0; mt < 4; ++mt)
                    ldsm4(a[mt], aAddr0 + mt * 16 * 208 + ks * 32);
                #pragma unroll
                for (int np = 0; np < 2; ++np) {
                    ldsm4(t, bAddr0 + np * 16 * 208 + ks * 32);
                    bh[2 * np + 0][0] = t[0]; bh[2 * np + 1][0] = t[1];
                    bh[2 * np + 0][1] = t[2]; bh[2 * np + 1][1] = t[3];
                    ldsm4(t, bAddr0 + (OFF_BL - OFF_BH) + np * 16 * 208 + ks * 32);
                    bl[2 * np + 0][0] = t[0]; bl[2 * np + 1][0] = t[1];
                    bl[2 * np + 0][1] = t[2]; bl[2 * np + 1][1] = t[3];
                }
                #pragma unroll
                for (int mt = 0; mt < 4; ++mt)
                    #pragma unroll
                    for (int nt = 0; nt < 4; ++nt) {
                        hmma(acc[mt][nt], a[mt], bh[nt]);
                        hmma(acc[mt][nt], a[mt], bl[nt]);
                    }
            }

            // epilogue: this CTA's 128-col half (streaming stores)
            float* outp = out + (size_t)p * (CCH * NOUT) + nh * 128;
            const int r0 = wm * 64 + (lane >> 2);
            const int c0 = wn * 32 + 2 * (lane & 3);
            float2 bv[4];
            #pragma unroll
            for (int nt = 0; nt < 4; ++nt)
                bv[nt] = *(const float2*)(bs + c0 + nt * 8);
            #pragma unroll
            for (int mt = 0; mt < 4; ++mt) {
                const int row = r0 + mt * 16;
                #pragma unroll
                for (int nt = 0; nt < 4; ++nt) {
                    const int col = c0 + nt * 8;
                    stcs2(outp + (size_t)row * NOUT + col,
                          acc[mt][nt][0] + bv[nt].x, acc[mt][nt][1] + bv[nt].y);
                    stcs2(outp + (size_t)(row + 8) * NOUT + col,
                          acc[mt][nt][2] + bv[nt].x, acc[mt][nt][3] + bv[nt].y);
                }
            }
        }

        if (nh == 1 && hasnext)
            gather_point(smem, cur ^ 1, An, tid);

        cur ^= 1;
    }
}

// ---------------------------------------------------------------------------
extern "C" void kernel_launch(void* const* d_in, const int* in_sizes, int n_in,
                              void* d_out, int out_size) {
    const float* points = (const float*)d_in[0];
    const float* feat0  = (const float*)d_in[1];
    const float* feat1  = (const float*)d_in[2];
    const float* feat2  = (const float*)d_in[3];
    const float* Wg     = (const float*)d_in[4];
    const float* biasg  = (const float*)d_in[5];
    float* out = (float*)d_out;

    prep_B_kernel<<<(NOUT * STRD + 255) / 256, 256>>>(Wg);

    cudaFuncSetAttribute(mlfs_kernel,
                         cudaFuncAttributeMaxDynamicSharedMemorySize, SMEM_TOTAL);
    mlfs_kernel<<<2 * NSM, NTHR, SMEM_TOTAL>>>(points, feat0, feat1, feat2,
                                               biasg, out);
}

// round 17
// speedup vs baseline: 1.8699x; 1.8699x over previous
#include <cuda_runtime.h>
#include <cuda_fp16.h>
#include <cstdint>

// ---------------------------------------------------------------------------
// MultiLevelFeatureSampler on GB300 (sm_103a via base-target sm_103 SASS)
//
// Per point: D[128x256] = P[128x83] @ W^T (+ bias); P = gather of 83 taps.
//
// R17: SINGLE-PRODUCT fp16 GEMM.  A -> fp16 (rounding err ~2.06e-4 measured
// in R11), B -> fp16 single rounding (adds independent ~2e-4 term; combined
// ~2.9e-4 < 1e-3 tolerance).  Halves HMMA work, cuts ldsm 33%, halves B smem.
// Structure is EXACT R11 (the 138us best): persistent CTAs (grid=148,
// 512 thr), gather of p+1 = fire-and-forget cp.async into raw fp32 smem
// during MMA of p, convert phase raw->fp16 A, resident B, st.global.cs.
// ---------------------------------------------------------------------------

#define NSM   148
#define NPTS_TOTAL 2048
#define CCH   128
#define DTOT  83
#define GTOT  (CCH * DTOT)     // 10624 gather elements per point
#define STRD  104              // row stride in fp16 (208 B, ldmatrix conflict-free)
#define NOUT  256
#define NTHR  512

#define H0 93
#define W0 305
#define H1 47
#define W1 153
#define H2 24
#define W2 77

// ---- smem layout (bytes) ----
#define OFF_TAPP    0                              // 83 * 8B tap base pointers
#define OFF_TAPS    672                            // 83 * 4B channel strides
#define OFF_BIAS    1008                           // 256 * 4B -> ends 2032
#define OFF_A       2048                           // 128 x 208B = 26624 (fp16)
#define OFF_RAW     (OFF_A + CCH * STRD * 2)       // 28672, 10624 fp32 = 42496
#define OFF_B       (OFF_RAW + GTOT * 4)           // 71168 (256 x 208B fp16)
#define SMEM_TOTAL  (OFF_B + NOUT * STRD * 2)      // 124416 (~121.5 KB)

// W fp16 scratch, row-major 256 x STRD (pads zeroed)
__device__ __align__(16) __half g_B[NOUT * STRD];

// ---------------------------------------------------------------------------
__device__ __forceinline__ uint32_t smem_u32(const void* p) {
    uint32_t a;
    asm("{ .reg .u64 t; cvta.to.shared.u64 t, %1; cvt.u32.u64 %0, t; }"
        : "=r"(a) : "l"(p));
    return a;
}

__device__ __forceinline__ void cp16(uint32_t dst, const void* src) {
    asm volatile("cp.async.cg.shared.global [%0], [%1], 16;"
                 :: "r"(dst), "l"(src) : "memory");
}

__device__ __forceinline__ void cp4(uint32_t dst, const void* src) {
    asm volatile("cp.async.ca.shared.global [%0], [%1], 4;"
                 :: "r"(dst), "l"(src) : "memory");
}

__device__ __forceinline__ void ldsm4(uint32_t* r, uint32_t addr) {
    asm volatile("ldmatrix.sync.aligned.m8n8.x4.shared.b16 {%0,%1,%2,%3}, [%4];"
                 : "=r"(r[0]), "=r"(r[1]), "=r"(r[2]), "=r"(r[3]) : "r"(addr));
}

__device__ __forceinline__ void hmma(float* c, const uint32_t* a, const uint32_t* b) {
    asm volatile(
        "mma.sync.aligned.m16n8k16.row.col.f32.f16.f16.f32 "
        "{%0,%1,%2,%3}, {%4,%5,%6,%7}, {%8,%9}, {%0,%1,%2,%3};"
        : "+f"(c[0]), "+f"(c[1]), "+f"(c[2]), "+f"(c[3])
        : "r"(a[0]), "r"(a[1]), "r"(a[2]), "r"(a[3]), "r"(b[0]), "r"(b[1]));
}

__device__ __forceinline__ void stcs2(float* p, float x, float y) {
    asm volatile("st.global.cs.v2.f32 [%0], {%1, %2};"
                 :: "l"(p), "f"(x), "f"(y) : "memory");
}

// Per-tap gather metadata for point pn (called with d < 83)
__device__ __forceinline__ void compute_taps(char* smem, int d, int pn,
                                             const float* __restrict__ points,
                                             const float* __restrict__ feat0,
                                             const float* __restrict__ feat1,
                                             const float* __restrict__ feat2) {
    const float* f; int H, Wd, ks, dd;
    if (d < 49)      { f = feat0; H = H0; Wd = W0; ks = 7; dd = d; }
    else if (d < 74) { f = feat1; H = H1; Wd = W1; ks = 5; dd = d - 49; }
    else             { f = feat2; H = H2; Wd = W2; ks = 3; dd = d - 74; }
    int half = ks >> 1;
    int jj = dd / ks - half;
    int kk = dd % ks - half;
    int bi = pn >> 9;
    float px = points[pn * 2 + 0];
    float py = points[pn * 2 + 1];
    float x = fminf(fmaxf(px * (float)(Wd - 1), 0.f), (float)(Wd - 1));
    float y = fminf(fmaxf(py * (float)(H  - 1), 0.f), (float)(H  - 1));
    int ox = (int)floorf(fminf(fmaxf(x + (float)kk, 0.f), (float)(Wd - 1)));
    int oy = (int)floorf(fminf(fmaxf(y + (float)jj, 0.f), (float)(H  - 1)));
    *(int*)(smem + OFF_TAPS + d * 4) = H * Wd;
    *(const float**)(smem + OFF_TAPP + d * 8) =
        f + (size_t)bi * CCH * H * Wd + (oy * Wd + ox);
}

// Issue all gather cp.asyncs for one point into the raw buffer (no waiting).
// 512 threads: e = tid + 512*i;  512 = 6*83 + 14.
__device__ __forceinline__ void issue_gather(char* smem, uint32_t raw, int tid) {
    int c = tid / DTOT;
    int d = tid - c * DTOT;
    #pragma unroll 7
    for (int i = 0; i < 21; ++i) {
        int e = tid + NTHR * i;
        if (e < GTOT) {
            const float* bp = *(const float* const*)(smem + OFF_TAPP + d * 8);
            int st = *(const int*)(smem + OFF_TAPS + d * 4);
            cp4(raw + e * 4, bp + (size_t)c * st);
        }
        c += 6; d += 14;
        if (d >= DTOT) { d -= DTOT; c += 1; }
    }
}

// Convert raw fp32 gather buffer -> fp16 A.
__device__ __forceinline__ void convert_raw(char* smem, int tid) {
    const float* raw = (const float*)(smem + OFF_RAW);
    char* ah = smem + OFF_A;
    int c = tid / DTOT;
    int d = tid - c * DTOT;
    #pragma unroll 7
    for (int i = 0; i < 21; ++i) {
        int e = tid + NTHR * i;
        if (e < GTOT) {
            *(__half*)(ah + c * 208 + d * 2) = __float2half(raw[e]);
        }
        c += 6; d += 14;
        if (d >= DTOT) { d -= DTOT; c += 1; }
    }
}

// ---------------------------------------------------------------------------
// Prologue: W (256x83 fp32) -> g_B fp16, row stride STRD, pads zeroed.
__global__ void prep_B_kernel(const float* __restrict__ Wg) {
    int idx = blockIdx.x * 256 + threadIdx.x;
    if (idx >= NOUT * STRD) return;
    int row = idx / STRD;
    int col = idx - row * STRD;
    float v = (col < DTOT) ? Wg[row * DTOT + col] : 0.f;
    g_B[idx] = __float2half(v);
}

// ---------------------------------------------------------------------------
__global__ void __launch_bounds__(NTHR, 1)
mlfs_kernel(const float* __restrict__ points,
            const float* __restrict__ feat0,
            const float* __restrict__ feat1,
            const float* __restrict__ feat2,
            const float* __restrict__ biasg,
            float* __restrict__ out) {
    extern __shared__ char smem[];
    const uint32_t smem_base = smem_u32(smem);
    const int tid = threadIdx.x;
    const int wid = tid >> 5;
    const int lane = tid & 31;
    const int r = blockIdx.x;

    // ---- setup: B resident copy (async), bias, A-pad zero ----
    {
        const char* src = (const char*)g_B;
        uint32_t dst = smem_base + OFF_B;
        const int n16 = (NOUT * STRD * 2) / 16;    // 3328
        #pragma unroll 2
        for (int i = tid; i < n16; i += NTHR)
            cp16(dst + i * 16, src + (size_t)i * 16);
    }
    if (tid < 64)
        ((float4*)(smem + OFF_BIAS))[tid] = ((const float4*)biasg)[tid];

    // zero A pad bytes 160..207 of every row (cols 80..103; convert rewrites
    // 80..82 each point): 128 rows, tid<128
    if (tid < 128) {
        float4 z = make_float4(0.f, 0.f, 0.f, 0.f);
        char* base = smem + OFF_A + tid * 208 + 160;
        ((float4*)base)[0] = z; ((float4*)base)[1] = z; ((float4*)base)[2] = z;
    }

    // taps for first point, then issue its gather
    if (tid < DTOT)
        compute_taps(smem, tid, r, points, feat0, feat1, feat2);
    __syncthreads();
    issue_gather(smem, smem_base + OFF_RAW, tid);
    asm volatile("cp.async.commit_group;" ::: "memory");

    // ---- persistent loop ----
    const int wm = wid >> 2;            // 0..3 (M, 32-row tiles)
    const int wn = wid & 3;             // 0..3 (N, 32-col tiles within half)
    const uint32_t lrow = lane & 15;
    const uint32_t kof2 = ((lane >> 4) << 3) * 2;
    const float* bs = (const float*)(smem + OFF_BIAS);

    for (int p = r; p < NPTS_TOTAL; p += NSM) {
        const int pn = p + NSM;
        const bool hasnext = (pn < NPTS_TOTAL);

        asm volatile("cp.async.wait_group 0;" ::: "memory");
        __syncthreads();                 // raw ready; MMA of p-1 done with A

        convert_raw(smem, tid);          // raw -> fp16 A  (raw now free)
        if (tid < DTOT && hasnext)
            compute_taps(smem, tid, pn, points, feat0, feat1, feat2);
        __syncthreads();                 // A ready; taps ready; raw free

        if (hasnext) {
            issue_gather(smem, smem_base + OFF_RAW, tid);   // fire and forget
            asm volatile("cp.async.commit_group;" ::: "memory");
        }

        // ---- single-product MMA + epilogue (R11 skeleton minus bl) ----
        float* outp = out + (size_t)p * (CCH * NOUT);
        #pragma unroll
        for (int hh = 0; hh < 2; ++hh) {
            float acc[2][4][4];
            #pragma unroll
            for (int mt = 0; mt < 2; ++mt)
                #pragma unroll
                for (int nt = 0; nt < 4; ++nt)
                    #pragma unroll
                    for (int q = 0; q < 4; ++q) acc[mt][nt][q] = 0.f;

            const uint32_t aAddr0 = smem_base + OFF_A
                                  + (wm * 32 + lrow) * 208 + kof2;
            const uint32_t bAddrH = smem_base + OFF_B
                                  + (hh * 128 + wn * 32 + lrow) * 208 + kof2;
            #pragma unroll
            for (int ks = 0; ks < 6; ++ks) {
                uint32_t a[2][4], bh[4][2], t[4];
                #pragma unroll
                for (int mt = 0; mt < 2; ++mt)
                    ldsm4(a[mt], aAddr0 + mt * 16 * 208 + ks * 32);
                #pragma unroll
                for (int np = 0; np < 2; ++np) {
                    ldsm4(t, bAddrH + np * 16 * 208 + ks * 32);
                    bh[2 * np + 0][0] = t[0]; bh[2 * np + 1][0] = t[1];
                    bh[2 * np + 0][1] = t[2]; bh[2 * np + 1][1] = t[3];
                }
                #pragma unroll
                for (int mt = 0; mt < 2; ++mt)
                    #pragma unroll
                    for (int nt = 0; nt < 4; ++nt)
                        hmma(acc[mt][nt], a[mt], bh[nt]);
            }

            // epilogue for this 128-col half (streaming stores)
            const int r0 = wm * 32 + (lane >> 2);
            const int c0 = wn * 32 + 2 * (lane & 3);
            float2 bv[4];
            #pragma unroll
            for (int nt = 0; nt < 4; ++nt)
                bv[nt] = *(const float2*)(bs + hh * 128 + c0 + nt * 8);
            float* oph = outp + hh * 128;
            #pragma unroll
            for (int mt = 0; mt < 2; ++mt) {
                const int row = r0 + mt * 16;
                #pragma unroll
                for (int nt = 0; nt < 4; ++nt) {
                    const int col = c0 + nt * 8;
                    stcs2(oph + (size_t)row * NOUT + col,
                          acc[mt][nt][0] + bv[nt].x, acc[mt][nt][1] + bv[nt].y);
                    stcs2(oph + (size_t)(row + 8) * NOUT + col,
                          acc[mt][nt][2] + bv[nt].x, acc[mt][nt][3] + bv[nt].y);
                }
            }
        }
    }
}

// ---------------------------------------------------------------------------
extern "C" void kernel_launch(void* const* d_in, const int* in_sizes, int n_in,
                              void* d_out, int out_size) {
    const float* points = (const float*)d_in[0];
    const float* feat0  = (const float*)d_in[1];
    const float* feat1  = (const float*)d_in[2];
    const float* feat2  = (const float*)d_in[3];
    const float* Wg     = (const float*)d_in[4];
    const float* biasg  = (const float*)d_in[5];
    float* out = (float*)d_out;

    prep_B_kernel<<<(NOUT * STRD + 255) / 256, 256>>>(Wg);

    cudaFuncSetAttribute(mlfs_kernel,
                         cudaFuncAttributeMaxDynamicSharedMemorySize, SMEM_TOTAL);
    mlfs_kernel<<<NSM, NTHR, SMEM_TOTAL>>>(points, feat0, feat1, feat2,
                                           biasg, out);
}